// round 1
// baseline (speedup 1.0000x reference)
#include <cuda_runtime.h>

#define T_       4
#define B_       2
#define C_       256
#define H_       56
#define W_       56
#define HEADS    8
#define D_       32
#define WIN_W    28
#define SPATIAL  (H_ * W_)        // 3136
#define NBW      128              // T*B*HEADS*2 windows

// phase 1: chunks of 4 image rows (112 positions)
#define ROWS1    4
#define POS1     112
#define PITCH1   116
#define NCH1     14               // 56 / 4

// phase 2: chunks of 8 image rows (224 positions)
#define ROWS2    8
#define POS2     224
#define PITCH2   228
#define NCH2     7                // 56 / 8

#define SCALE2   0.35355339059327373f   // 2 / sqrt(32)

// scratch (static device memory — no allocations)
__device__ float g_Ppart[NBW * NCH1 * 1024];   // per-chunk partial K^T V
__device__ float g_P[NBW * 1024];              // reduced + scaled K^T V

__device__ __forceinline__ void fma2(unsigned long long& d,
                                     unsigned long long a,
                                     unsigned long long b) {
    asm("fma.rn.f32x2 %0, %1, %2, %0;" : "+l"(d) : "l"(a), "l"(b));
}
__device__ __forceinline__ unsigned long long rep2(float x) {
    unsigned long long r;
    asm("mov.b64 %0, {%1, %1};" : "=l"(r) : "f"(x));
    return r;
}
__device__ __forceinline__ float lo32(unsigned long long x) {
    return __uint_as_float((unsigned)x);
}
__device__ __forceinline__ float hi32(unsigned long long x) {
    return __uint_as_float((unsigned)(x >> 32));
}

// ---------------------------------------------------------------------------
// Phase 1: partial P = K^T V per (batch-window, 4-row chunk)
// ---------------------------------------------------------------------------
__global__ __launch_bounds__(256, 2)
void phase1_kv(const float* __restrict__ K, const float* __restrict__ V) {
    __shared__ float ks[32][PITCH1];
    __shared__ float vs[32][PITCH1];
    __shared__ float red[4][1024];

    const int tid   = threadIdx.x;
    const int bw    = blockIdx.x;      // 0..127
    const int chunk = blockIdx.y;      // 0..13
    const int win   = bw & 1;
    const int head  = (bw >> 1) & 7;
    const int tb    = bw >> 4;
    const int base  = (tb * C_ + head * D_) * SPATIAL
                    + (chunk * ROWS1) * W_ + win * WIN_W;

    // stage K,V tile: 32 channels x 112 positions (896 float4s)
    #pragma unroll
    for (int it = 0; it < 4; it++) {
        int idx4 = it * 256 + tid;
        if (idx4 < 896) {
            int c  = idx4 / 28;
            int p  = (idx4 % 28) * 4;        // 0..108, multiple of 4
            int r  = p / WIN_W;
            int ww = p - r * WIN_W;
            int g  = base + c * SPATIAL + r * W_ + ww;
            *(float4*)&ks[c][p] = *(const float4*)(K + g);
            *(float4*)&vs[c][p] = *(const float4*)(V + g);
        }
    }
    __syncthreads();

    const int c1g  = tid & 7;
    const int c2g  = (tid >> 3) & 7;
    const int posg = tid >> 6;       // 0..3

    unsigned long long acc[4][4][2];
    #pragma unroll
    for (int i = 0; i < 4; i++)
        #pragma unroll
        for (int j = 0; j < 4; j++) { acc[i][j][0] = 0ull; acc[i][j][1] = 0ull; }

    #pragma unroll
    for (int s = 0; s < 7; s++) {
        const int pbase = (posg + s * 4) * 4;   // 0..108
        ulonglong2 kk[4], vv[4];
        #pragma unroll
        for (int i = 0; i < 4; i++)
            kk[i] = *(const ulonglong2*)&ks[c1g * 4 + i][pbase];
        #pragma unroll
        for (int j = 0; j < 4; j++)
            vv[j] = *(const ulonglong2*)&vs[c2g * 4 + j][pbase];
        #pragma unroll
        for (int i = 0; i < 4; i++)
            #pragma unroll
            for (int j = 0; j < 4; j++) {
                fma2(acc[i][j][0], kk[i].x, vv[j].x);
                fma2(acc[i][j][1], kk[i].y, vv[j].y);
            }
    }
    __syncthreads();

    #pragma unroll
    for (int i = 0; i < 4; i++)
        #pragma unroll
        for (int j = 0; j < 4; j++) {
            unsigned long long a = acc[i][j][0], b = acc[i][j][1];
            red[posg][(c1g * 4 + i) * 32 + c2g * 4 + j] =
                lo32(a) + hi32(a) + lo32(b) + hi32(b);
        }
    __syncthreads();

    for (int o = tid; o < 1024; o += 256) {
        float s = red[0][o] + red[1][o] + red[2][o] + red[3][o];
        g_Ppart[(bw * NCH1 + chunk) * 1024 + o] = s;
    }
}

// ---------------------------------------------------------------------------
// Mid: reduce 14 chunk partials -> P, apply scale
// ---------------------------------------------------------------------------
__global__ __launch_bounds__(256)
void phase_mid() {
    const int bw = blockIdx.x;
    const int o  = threadIdx.x * 4;
    float4 s = make_float4(0.f, 0.f, 0.f, 0.f);
    #pragma unroll
    for (int ch = 0; ch < NCH1; ch++) {
        const float4 p4 = *(const float4*)&g_Ppart[(bw * NCH1 + ch) * 1024 + o];
        s.x += p4.x; s.y += p4.y; s.z += p4.z; s.w += p4.w;
    }
    s.x *= SCALE2; s.y *= SCALE2; s.z *= SCALE2; s.w *= SCALE2;
    *(float4*)&g_P[bw * 1024 + o] = s;
}

// ---------------------------------------------------------------------------
// Phase 2: out = Q * P per (batch-window, 8-row chunk)
// ---------------------------------------------------------------------------
__global__ __launch_bounds__(256, 2)
void phase2_qp(const float* __restrict__ Q, float* __restrict__ O) {
    __shared__ float Ps[1024];
    __shared__ float qs[32][PITCH2];

    const int tid   = threadIdx.x;
    const int bw    = blockIdx.x;
    const int chunk = blockIdx.y;      // 0..6
    const int win   = bw & 1;
    const int head  = (bw >> 1) & 7;
    const int tb    = bw >> 4;
    const int base  = (tb * C_ + head * D_) * SPATIAL
                    + (chunk * ROWS2) * W_ + win * WIN_W;

    // load reduced P (32x32)
    *(float4*)&Ps[tid * 4] = *(const float4*)&g_P[bw * 1024 + tid * 4];

    // stage Q tile: 32 channels x 224 positions (1792 float4s)
    #pragma unroll
    for (int it = 0; it < 7; it++) {
        int idx4 = it * 256 + tid;
        int c  = idx4 / 56;
        int p  = (idx4 % 56) * 4;          // 0..220
        int r  = p / WIN_W;
        int ww = p - r * WIN_W;
        int g  = base + c * SPATIAL + r * W_ + ww;
        *(float4*)&qs[c][p] = *(const float4*)(Q + g);
    }
    __syncthreads();

    const int c2g  = tid & 7;
    const int posg = tid >> 3;             // 0..31, active < 28
    if (posg < 28) {
        unsigned long long acc[4][4];
        #pragma unroll
        for (int j = 0; j < 4; j++)
            #pragma unroll
            for (int h = 0; h < 4; h++) acc[j][h] = 0ull;

        const int pbase = posg * 8;        // 8 consecutive positions
        #pragma unroll
        for (int c1 = 0; c1 < 32; c1++) {
            ulonglong2 qa = *(const ulonglong2*)&qs[c1][pbase];
            ulonglong2 qb = *(const ulonglong2*)&qs[c1][pbase + 4];
            float4 pv = *(const float4*)&Ps[c1 * 32 + c2g * 4];
            unsigned long long pj;
            pj = rep2(pv.x);
            fma2(acc[0][0], qa.x, pj); fma2(acc[0][1], qa.y, pj);
            fma2(acc[0][2], qb.x, pj); fma2(acc[0][3], qb.y, pj);
            pj = rep2(pv.y);
            fma2(acc[1][0], qa.x, pj); fma2(acc[1][1], qa.y, pj);
            fma2(acc[1][2], qb.x, pj); fma2(acc[1][3], qb.y, pj);
            pj = rep2(pv.z);
            fma2(acc[2][0], qa.x, pj); fma2(acc[2][1], qa.y, pj);
            fma2(acc[2][2], qb.x, pj); fma2(acc[2][3], qb.y, pj);
            pj = rep2(pv.w);
            fma2(acc[3][0], qa.x, pj); fma2(acc[3][1], qa.y, pj);
            fma2(acc[3][2], qb.x, pj); fma2(acc[3][3], qb.y, pj);
        }

        #pragma unroll
        for (int j = 0; j < 4; j++) {
            const int c2 = c2g * 4 + j;
            #pragma unroll
            for (int h = 0; h < 2; h++) {
                const int pp = pbase + h * 4;
                const int r  = pp / WIN_W;
                const int ww = pp - r * WIN_W;
                float4 o4;
                o4.x = lo32(acc[j][h * 2]);
                o4.y = hi32(acc[j][h * 2]);
                o4.z = lo32(acc[j][h * 2 + 1]);
                o4.w = hi32(acc[j][h * 2 + 1]);
                *(float4*)(O + base + c2 * SPATIAL + r * W_ + ww) = o4;
            }
        }
    }
}

// ---------------------------------------------------------------------------
extern "C" void kernel_launch(void* const* d_in, const int* in_sizes, int n_in,
                              void* d_out, int out_size) {
    const float* q = (const float*)d_in[0];
    const float* k = (const float*)d_in[1];
    const float* v = (const float*)d_in[2];
    float* out = (float*)d_out;

    phase1_kv<<<dim3(NBW, NCH1), 256>>>(k, v);
    phase_mid<<<NBW, 256>>>();
    phase2_qp<<<dim3(NBW, NCH2), 256>>>(q, out);
}

// round 3
// speedup vs baseline: 1.8379x; 1.8379x over previous
#include <cuda_runtime.h>

#define SPATIAL  3136            // 56*56
#define NBW      128             // T*B*heads*2 windows
#define SCALE2   0.35355339059327373f   // 2/sqrt(32)

// phase1: chunks of 8 image rows = 224 positions = 112 pairs = 56 16B-chunks/row
#define P1_CHUNKS     7
#define P1_ROWB       896                 // 56 chunks * 16B per channel-row
#define P1_TENSOR     (32 * P1_ROWB)      // 28672 B per tensor tile
#define P1_BUF        (2 * P1_TENSOR)     // 57344 B per double-buffer slot
#define P1_SMEM       (2 * P1_BUF)        // 114688 B total
#define P1_LINES      1792                // 32 ch * 56 chunks per tensor

// reduction buffer layout (reuses buf1 region): 4 bufs of 32x34 floats
#define RED_PITCH 34
#define RED_BUF   (32 * RED_PITCH)        // 1088 floats

__device__ float g_P[NBW * 1024];         // scaled K^T V per batch-window

typedef unsigned long long ull;

__device__ __forceinline__ void fma2(ull& d, ull a, ull b) {
    asm("fma.rn.f32x2 %0, %1, %2, %0;" : "+l"(d) : "l"(a), "l"(b));
}
__device__ __forceinline__ ull rep2(float x) {
    ull r; asm("mov.b64 %0, {%1, %1};" : "=l"(r) : "f"(x)); return r;
}
__device__ __forceinline__ float lo32(ull x) { return __uint_as_float((unsigned)x); }
__device__ __forceinline__ float hi32(ull x) { return __uint_as_float((unsigned)(x >> 32)); }

__device__ __forceinline__ void cp16(unsigned dst, const void* src) {
    asm volatile("cp.async.cg.shared.global [%0], [%1], 16;" :: "r"(dst), "l"(src));
}

// ---------------------------------------------------------------------------
// Phase 1: P = scale * K^T V per batch-window. One block per bw, persistent
// accumulators across 7 chunks of 224 positions, cp.async double buffering.
// ---------------------------------------------------------------------------
__global__ __launch_bounds__(256, 1)
void phase1(const float* __restrict__ K, const float* __restrict__ V) {
    extern __shared__ __align__(16) char sm[];
    const unsigned sm32 = (unsigned)__cvta_generic_to_shared(sm);

    const int tid  = threadIdx.x;
    const int bw   = blockIdx.x;
    const int win  = bw & 1;
    const int head = (bw >> 1) & 7;
    const int tb   = bw >> 4;
    const int base = (tb * 256 + head * 32) * SPATIAL + win * 28;   // float index

    const int ti   = tid & 3;          // c1 tile group
    const int tj   = (tid >> 2) & 3;   // c2 tile group
    const int posg = tid >> 4;         // 0..15 position-pair groups

    // ---- staging helper: 14 cp.asyncs per thread per chunk ----
    auto stage = [&](int ch, int buf) {
        const unsigned bufb = sm32 + buf * P1_BUF;
        const int gofs = base + ch * 448;           // 8 rows * 56
        #pragma unroll
        for (int it = 0; it < 14; it++) {
            int idx = it * 256 + tid;               // 0..3583
            int tensor = (idx >= P1_LINES) ? 1 : 0; // 0=K, 1=V  (1792 lines each)
            int rem = idx - tensor * P1_LINES;      // 0..1791
            int c = rem / 56;
            int g = rem - c * 56;
            int r = g / 7;
            int w4 = g - r * 7;
            const float* src = (tensor ? V : K) + gofs + c * SPATIAL + r * 56 + w4 * 4;
            int chs = g ^ (((c >> 3) & 3) << 1);    // XOR swizzle keyed on c>>3
            unsigned dst = bufb + tensor * P1_TENSOR + c * P1_ROWB + chs * 16;
            cp16(dst, src);
        }
        asm volatile("cp.async.commit_group;");
    };

    ull acc[8][8];
    #pragma unroll
    for (int i = 0; i < 8; i++)
        #pragma unroll
        for (int j = 0; j < 8; j++) acc[i][j] = 0ull;

    stage(0, 0);

    const int xk = ti << 1;   // swizzle key for k rows
    const int xv = tj << 1;   // swizzle key for v rows

    for (int ch = 0; ch < P1_CHUNKS; ch++) {
        if (ch < P1_CHUNKS - 1) {
            stage(ch + 1, (ch + 1) & 1);
            asm volatile("cp.async.wait_group 1;");
        } else {
            asm volatile("cp.async.wait_group 0;");
        }
        __syncthreads();

        const char* kB = sm + (ch & 1) * P1_BUF;
        const char* vB = kB + P1_TENSOR;

        #pragma unroll
        for (int u = 0; u < 7; u++) {
            const int pr = posg + u * 16;             // pair index 0..111
            const unsigned sub  = (pr & 1) << 3;
            const unsigned offk = ((unsigned)((pr >> 1) ^ xk) << 4) + sub;
            const unsigned offv = ((unsigned)((pr >> 1) ^ xv) << 4) + sub;
            ull kk[8], vv[8];
            #pragma unroll
            for (int i = 0; i < 8; i++)
                kk[i] = *(const ull*)(kB + (ti * 8 + i) * P1_ROWB + offk);
            #pragma unroll
            for (int j = 0; j < 8; j++)
                vv[j] = *(const ull*)(vB + (tj * 8 + j) * P1_ROWB + offv);
            #pragma unroll
            for (int i = 0; i < 8; i++)
                #pragma unroll
                for (int j = 0; j < 8; j++)
                    fma2(acc[i][j], kk[i], vv[j]);
        }
        __syncthreads();
    }

    // ---- reduction: horizontal pair add, xor-16 shuffle, 8->1 warp tree ----
    float r[8][8];
    #pragma unroll
    for (int i = 0; i < 8; i++)
        #pragma unroll
        for (int j = 0; j < 8; j++) {
            float s = lo32(acc[i][j]) + hi32(acc[i][j]);
            s += __shfl_xor_sync(0xffffffffu, s, 16);
            r[i][j] = s;
        }

    const int lane = tid & 31, wid = tid >> 5;
    const bool act = lane < 16;
    float* red = (float*)(sm + P1_BUF);     // buf1 region is free after last chunk
    const int prow0 = ti * 8, pcol0 = tj * 8;
    #define RIDX(i, j) ((prow0 + (i)) * RED_PITCH + pcol0 + (j))

    if (act && wid >= 4)
        #pragma unroll
        for (int i = 0; i < 8; i++)
            #pragma unroll
            for (int j = 0; j < 8; j++) red[(wid - 4) * RED_BUF + RIDX(i, j)] = r[i][j];
    __syncthreads();
    if (act && wid < 4)
        #pragma unroll
        for (int i = 0; i < 8; i++)
            #pragma unroll
            for (int j = 0; j < 8; j++) r[i][j] += red[wid * RED_BUF + RIDX(i, j)];
    __syncthreads();
    if (act && (wid == 2 || wid == 3))
        #pragma unroll
        for (int i = 0; i < 8; i++)
            #pragma unroll
            for (int j = 0; j < 8; j++) red[(wid - 2) * RED_BUF + RIDX(i, j)] = r[i][j];
    __syncthreads();
    if (act && wid < 2)
        #pragma unroll
        for (int i = 0; i < 8; i++)
            #pragma unroll
            for (int j = 0; j < 8; j++) r[i][j] += red[wid * RED_BUF + RIDX(i, j)];
    __syncthreads();
    if (act && wid == 1)
        #pragma unroll
        for (int i = 0; i < 8; i++)
            #pragma unroll
            for (int j = 0; j < 8; j++) red[RIDX(i, j)] = r[i][j];
    __syncthreads();
    if (act && wid == 0) {
        float* gp = g_P + bw * 1024;
        #pragma unroll
        for (int i = 0; i < 8; i++)
            #pragma unroll
            for (int j = 0; j < 8; j++)
                gp[(prow0 + i) * 32 + pcol0 + j] =
                    (r[i][j] + red[RIDX(i, j)]) * SCALE2;
    }
    #undef RIDX
}

// ---------------------------------------------------------------------------
// Phase 2: out = Q * P. Grid (128 bw, 7 chunks of 8 rows), 128 threads.
// Thread tile: 8 consecutive positions x 8 channels, f32x2 over pos pairs.
// ---------------------------------------------------------------------------
__global__ __launch_bounds__(128)
void phase2(const float* __restrict__ Q, float* __restrict__ O) {
    __shared__ __align__(16) float qs[32 * 224];
    __shared__ __align__(16) float ps[1024];

    const int tid = threadIdx.x;
    const int bw  = blockIdx.x;
    const int ck  = blockIdx.y;
    const int win  = bw & 1;
    const int head = (bw >> 1) & 7;
    const int tb   = bw >> 4;
    const int base = (tb * 256 + head * 32) * SPATIAL + win * 28 + ck * 448;

    // stage P (1024 floats)
    #pragma unroll
    for (int t = 0; t < 2; t++) {
        int i4 = tid + t * 128;
        *(float4*)&ps[i4 * 4] = *(const float4*)&g_P[bw * 1024 + i4 * 4];
    }
    // stage Q tile: 32 channels x 224 positions
    #pragma unroll
    for (int it = 0; it < 14; it++) {
        int idx = it * 128 + tid;
        int c = idx / 56;
        int g = idx - c * 56;
        int r = g / 7;
        int w4 = g - r * 7;
        *(float4*)&qs[c * 224 + g * 4] =
            *(const float4*)(Q + base + c * SPATIAL + r * 56 + w4 * 4);
    }
    __syncthreads();

    const int c2g  = tid & 3;
    const int posg = tid >> 2;          // 0..31, active < 28
    if (posg >= 28) return;
    const int pbase = posg * 8;

    ull a[4][8];
    #pragma unroll
    for (int p = 0; p < 4; p++)
        #pragma unroll
        for (int j = 0; j < 8; j++) a[p][j] = 0ull;

    #pragma unroll
    for (int c1 = 0; c1 < 32; c1++) {
        ulonglong2 qa = *(const ulonglong2*)&qs[c1 * 224 + pbase];
        ulonglong2 qb = *(const ulonglong2*)&qs[c1 * 224 + pbase + 4];
        float4 p0 = *(const float4*)&ps[c1 * 32 + c2g * 8];
        float4 p1 = *(const float4*)&ps[c1 * 32 + c2g * 8 + 4];
        const float pv[8] = {p0.x, p0.y, p0.z, p0.w, p1.x, p1.y, p1.z, p1.w};
        #pragma unroll
        for (int j = 0; j < 8; j++) {
            ull pj = rep2(pv[j]);
            fma2(a[0][j], qa.x, pj);
            fma2(a[1][j], qa.y, pj);
            fma2(a[2][j], qb.x, pj);
            fma2(a[3][j], qb.y, pj);
        }
    }

    #pragma unroll
    for (int j = 0; j < 8; j++) {
        const int c2 = c2g * 8 + j;
        #pragma unroll
        for (int h = 0; h < 2; h++) {
            const int p  = pbase + h * 4;
            const int rr = p / 28;
            const int ww = p - rr * 28;
            float4 o4;
            o4.x = lo32(a[2 * h][j]);
            o4.y = hi32(a[2 * h][j]);
            o4.z = lo32(a[2 * h + 1][j]);
            o4.w = hi32(a[2 * h + 1][j]);
            *(float4*)(O + base + c2 * SPATIAL + rr * 56 + ww) = o4;
        }
    }
}

// ---------------------------------------------------------------------------
extern "C" void kernel_launch(void* const* d_in, const int* in_sizes, int n_in,
                              void* d_out, int out_size) {
    const float* q = (const float*)d_in[0];
    const float* k = (const float*)d_in[1];
    const float* v = (const float*)d_in[2];
    float* out = (float*)d_out;

    cudaFuncSetAttribute(phase1, cudaFuncAttributeMaxDynamicSharedMemorySize, P1_SMEM);

    phase1<<<NBW, 256, P1_SMEM>>>(k, v);
    phase2<<<dim3(NBW, 7), 128>>>(q, out);
}